// round 1
// baseline (speedup 1.0000x reference)
#include <cuda_runtime.h>
#include <cuda_bf16.h>

#define C 128
#define C4 32          // float4 per row
#define MAX_N 100000
#define BM 64          // GEMM rows per block
#define GEMM_SMEM ((128*128 + BM*129) * 4)   // 98560 bytes

// ---------------- scratch (device globals; no allocation allowed) ------------
__device__ float g_temb[C];
__device__ float g_deg[MAX_N];
__device__ float g_dinv[MAX_N];
__device__ float g_bufA[(size_t)MAX_N * C];
__device__ float g_bufB[(size_t)MAX_N * C];

// ---------------- time embedding: relu(t*W1+b1) @ W2 + b2 --------------------
__global__ void temb_kernel(const float* __restrict__ t,
                            const float* __restrict__ tW1, const float* __restrict__ tb1,
                            const float* __restrict__ tW2, const float* __restrict__ tb2) {
    __shared__ float hid[C];
    int j = threadIdx.x;
    float tv = t[0];
    hid[j] = fmaxf(tv * tW1[j] + tb1[j], 0.0f);
    __syncthreads();
    float s = tb2[j];
#pragma unroll 8
    for (int i = 0; i < C; i++) s += hid[i] * tW2[i * C + j];
    g_temb[j] = s;
}

// ---------------- degree / dinv ----------------------------------------------
__global__ void deg_init_kernel(int N) {
    int i = blockIdx.x * blockDim.x + threadIdx.x;
    if (i < N) g_deg[i] = 1.0f;           // self loop
}
__global__ void deg_count_kernel(const int* __restrict__ dst, int E) {
    int e = blockIdx.x * blockDim.x + threadIdx.x;
    if (e < E) atomicAdd(&g_deg[dst[e]], 1.0f);
}
__global__ void dinv_kernel(int N) {
    int i = blockIdx.x * blockDim.x + threadIdx.x;
    if (i < N) g_dinv[i] = rsqrtf(g_deg[i]);
}

// ---------------- GEMM: out[M,128] = (A + temb?) @ W[128,128] ----------------
// BM=64 rows per block, 256 threads, each thread computes 4 rows x 8 cols.
__global__ void gemm_kernel(const float* __restrict__ A, const float* __restrict__ W,
                            float* __restrict__ out, int M, int add_temb) {
    extern __shared__ float smem[];
    float* wS = smem;              // 128*128
    float* aS = smem + 128 * 128;  // BM * 129 (padded)
    int tid = threadIdx.x;
    int row0 = blockIdx.x * BM;

    // load W (4096 float4, 16 per thread)
    const float4* W4 = (const float4*)W;
    float4* wS4 = (float4*)wS;
#pragma unroll
    for (int i = 0; i < 16; i++) wS4[tid + i * 256] = W4[tid + i * 256];

    // load A tile (2048 float4, 8 per thread) with optional broadcast temb add
#pragma unroll
    for (int i = 0; i < 8; i++) {
        int idx = tid + i * 256;       // 0..2047
        int r = idx >> 5;              // row in tile
        int c = idx & 31;              // float4 col
        float4 v = make_float4(0.f, 0.f, 0.f, 0.f);
        int row = row0 + r;
        if (row < M) v = ((const float4*)A)[(size_t)row * C4 + c];
        if (add_temb) {
            float4 tv = ((const float4*)g_temb)[c];
            v.x += tv.x; v.y += tv.y; v.z += tv.z; v.w += tv.w;
        }
        int base = r * 129 + c * 4;
        aS[base + 0] = v.x; aS[base + 1] = v.y; aS[base + 2] = v.z; aS[base + 3] = v.w;
    }
    __syncthreads();

    int tx = tid & 15;   // col group: cols tx*8 .. tx*8+7
    int ty = tid >> 4;   // row group: rows ty*4 .. ty*4+3 (warp = 2 ty values)
    float acc[4][8];
#pragma unroll
    for (int r = 0; r < 4; r++)
#pragma unroll
        for (int j = 0; j < 8; j++) acc[r][j] = 0.f;

    const float* aBase = &aS[(ty * 4) * 129];
#pragma unroll 8
    for (int k = 0; k < 128; k++) {
        float a0 = aBase[k];
        float a1 = aBase[129 + k];
        float a2 = aBase[258 + k];
        float a3 = aBase[387 + k];
        float4 w0 = wS4[k * 32 + tx * 2];
        float4 w1 = wS4[k * 32 + tx * 2 + 1];
        acc[0][0] += a0 * w0.x; acc[0][1] += a0 * w0.y; acc[0][2] += a0 * w0.z; acc[0][3] += a0 * w0.w;
        acc[0][4] += a0 * w1.x; acc[0][5] += a0 * w1.y; acc[0][6] += a0 * w1.z; acc[0][7] += a0 * w1.w;
        acc[1][0] += a1 * w0.x; acc[1][1] += a1 * w0.y; acc[1][2] += a1 * w0.z; acc[1][3] += a1 * w0.w;
        acc[1][4] += a1 * w1.x; acc[1][5] += a1 * w1.y; acc[1][6] += a1 * w1.z; acc[1][7] += a1 * w1.w;
        acc[2][0] += a2 * w0.x; acc[2][1] += a2 * w0.y; acc[2][2] += a2 * w0.z; acc[2][3] += a2 * w0.w;
        acc[2][4] += a2 * w1.x; acc[2][5] += a2 * w1.y; acc[2][6] += a2 * w1.z; acc[2][7] += a2 * w1.w;
        acc[3][0] += a3 * w0.x; acc[3][1] += a3 * w0.y; acc[3][2] += a3 * w0.z; acc[3][3] += a3 * w0.w;
        acc[3][4] += a3 * w1.x; acc[3][5] += a3 * w1.y; acc[3][6] += a3 * w1.z; acc[3][7] += a3 * w1.w;
    }

#pragma unroll
    for (int r = 0; r < 4; r++) {
        int orow = row0 + ty * 4 + r;
        if (orow < M) {
            float4* o = (float4*)(out + (size_t)orow * C + tx * 8);
            o[0] = make_float4(acc[r][0], acc[r][1], acc[r][2], acc[r][3]);
            o[1] = make_float4(acc[r][4], acc[r][5], acc[r][6], acc[r][7]);
        }
    }
}

// ---------------- init: out = x * dinv^2 + bias ------------------------------
__global__ void agg_init_kernel(const float* __restrict__ x, float* __restrict__ out,
                                const float* __restrict__ bias, int M) {
    int idx = blockIdx.x * blockDim.x + threadIdx.x;   // over M*32 float4
    if (idx >= M * C4) return;
    int row = idx >> 5;
    int c = idx & 31;
    float di = g_dinv[row];
    float di2 = di * di;
    float4 v = ((const float4*)x)[idx];
    float4 b = ((const float4*)bias)[c];
    float4 o;
    o.x = v.x * di2 + b.x;
    o.y = v.y * di2 + b.y;
    o.z = v.z * di2 + b.z;
    o.w = v.w * di2 + b.w;
    ((float4*)out)[idx] = o;
}

// ---------------- scatter: out[dst] += x[src] * dinv[src]*dinv[dst] ----------
// one warp per edge, one float4 per lane, 16B vector atomics
__global__ void scatter_kernel(const float* __restrict__ x, float* __restrict__ out,
                               const int* __restrict__ src, const int* __restrict__ dst,
                               int E) {
    int gw = (blockIdx.x * blockDim.x + threadIdx.x) >> 5;
    int lane = threadIdx.x & 31;
    if (gw >= E) return;
    int s = src[gw];
    int d = dst[gw];
    float coef = g_dinv[s] * g_dinv[d];
    float4 v = ((const float4*)(x + (size_t)s * C))[lane];
    v.x *= coef; v.y *= coef; v.z *= coef; v.w *= coef;
    atomicAdd(((float4*)(out + (size_t)d * C)) + lane, v);
}

// ---------------- LayerNorm + ReLU (one warp per row) ------------------------
__global__ void ln_relu_kernel(const float* __restrict__ in, float* __restrict__ out,
                               const float* __restrict__ lnw, const float* __restrict__ lnb,
                               int M) {
    int row = (blockIdx.x * blockDim.x + threadIdx.x) >> 5;
    int lane = threadIdx.x & 31;
    if (row >= M) return;
    float4 v = ((const float4*)(in + (size_t)row * C))[lane];
    float s = v.x + v.y + v.z + v.w;
#pragma unroll
    for (int o = 16; o > 0; o >>= 1) s += __shfl_xor_sync(0xFFFFFFFFu, s, o);
    float mu = s * (1.0f / 128.0f);
    float dx = v.x - mu, dy = v.y - mu, dz = v.z - mu, dw = v.w - mu;
    float sq = dx * dx + dy * dy + dz * dz + dw * dw;
#pragma unroll
    for (int o = 16; o > 0; o >>= 1) sq += __shfl_xor_sync(0xFFFFFFFFu, sq, o);
    float rstd = rsqrtf(sq * (1.0f / 128.0f) + 1e-5f);
    float4 w = ((const float4*)lnw)[lane];
    float4 b = ((const float4*)lnb)[lane];
    float4 o;
    o.x = fmaxf(dx * rstd * w.x + b.x, 0.0f);
    o.y = fmaxf(dy * rstd * w.y + b.y, 0.0f);
    o.z = fmaxf(dz * rstd * w.z + b.z, 0.0f);
    o.w = fmaxf(dw * rstd * w.w + b.w, 0.0f);
    ((float4*)(out + (size_t)row * C))[lane] = o;
}

// ---------------- launcher ---------------------------------------------------
extern "C" void kernel_launch(void* const* d_in, const int* in_sizes, int n_in,
                              void* d_out, int out_size) {
    const float* h_noisy = (const float*)d_in[0];
    const int*   edge    = (const int*)  d_in[1];
    const float* t       = (const float*)d_in[2];
    const float* tW1     = (const float*)d_in[3];
    const float* tb1     = (const float*)d_in[4];
    const float* tW2     = (const float*)d_in[5];
    const float* tb2     = (const float*)d_in[6];
    const float* W1      = (const float*)d_in[7];
    const float* b1      = (const float*)d_in[8];
    const float* W2      = (const float*)d_in[9];
    const float* b2      = (const float*)d_in[10];
    const float* ln_w    = (const float*)d_in[11];
    const float* ln_b    = (const float*)d_in[12];
    float* out = (float*)d_out;

    int N = in_sizes[0] / C;
    int E = in_sizes[1] / 2;
    const int* src = edge;
    const int* dst = edge + E;

    float *bufA, *bufB;
    cudaGetSymbolAddress((void**)&bufA, g_bufA);
    cudaGetSymbolAddress((void**)&bufB, g_bufB);

    cudaFuncSetAttribute(gemm_kernel, cudaFuncAttributeMaxDynamicSharedMemorySize, GEMM_SMEM);

    // 1. time embedding
    temb_kernel<<<1, C>>>(t, tW1, tb1, tW2, tb2);

    // 2. degree -> dinv
    deg_init_kernel<<<(N + 255) / 256, 256>>>(N);
    deg_count_kernel<<<(E + 255) / 256, 256>>>(dst, E);
    dinv_kernel<<<(N + 255) / 256, 256>>>(N);

    int gemm_blocks = (N + BM - 1) / BM;
    int ew_blocks   = (N * C4 + 255) / 256;
    int sc_blocks   = (E * 32 + 255) / 256;
    int row_blocks  = (N * 32 + 255) / 256;

    // 3. x1 = (h + temb) @ W1   -> bufA
    gemm_kernel<<<gemm_blocks, 256, GEMM_SMEM>>>(h_noisy, W1, bufA, N, 1);
    // 4. bufB = x1*dinv^2 + b1 ; scatter edges into bufB
    agg_init_kernel<<<ew_blocks, 256>>>(bufA, bufB, b1, N);
    scatter_kernel<<<sc_blocks, 256>>>(bufA, bufB, src, dst, E);
    // 5. bufA = relu(LN(bufB))
    ln_relu_kernel<<<row_blocks, 256>>>(bufB, bufA, ln_w, ln_b, N);
    // 6. x2 = bufA @ W2 -> bufB
    gemm_kernel<<<gemm_blocks, 256, GEMM_SMEM>>>(bufA, W2, bufB, N, 0);
    // 7. out = x2*dinv^2 + b2 ; scatter edges into out
    agg_init_kernel<<<ew_blocks, 256>>>(bufB, out, b2, N);
    scatter_kernel<<<sc_blocks, 256>>>(bufB, out, src, dst, E);
}

// round 2
// speedup vs baseline: 1.8093x; 1.8093x over previous
#include <cuda_runtime.h>
#include <cuda_bf16.h>
#include <cstdint>

#define C 128
#define C4 32
#define MAX_N 100000
#define MAX_E 640000
#define BM 64
#define GEMM_THREADS 512
#define GEMM_SMEM (49152 * 4)   // Wb 16384 + Ws 16384 + Ab 8192 + As 8192 floats

// ---------------- scratch (device globals; no allocation allowed) ------------
__device__ float g_temb[C];
__device__ int   g_degi[MAX_N];
__device__ float g_dinv[MAX_N];
__device__ int   g_off[MAX_N + 1];
__device__ int   g_cur[MAX_N];
__device__ int   g_bsum[512];
__device__ int   g_csr_src[MAX_E];
__device__ float g_csr_coef[MAX_E];
__device__ float g_bufA[(size_t)MAX_N * C];
__device__ float g_bufB[(size_t)MAX_N * C];
__device__ float g_wb[2][16384];   // W big parts, fragment-major
__device__ float g_ws[2][16384];   // W small parts, fragment-major

// ---------------- helpers ----------------------------------------------------
__device__ __forceinline__ unsigned f2tf(float f) {
    unsigned u;
    asm("cvt.rna.tf32.f32 %0, %1;" : "=r"(u) : "f"(f));
    return u;
}

__device__ __forceinline__ void mma8(float* c, unsigned a0, unsigned a1,
                                     unsigned a2, unsigned a3,
                                     unsigned b0, unsigned b1) {
    asm volatile(
        "mma.sync.aligned.m16n8k8.row.col.f32.tf32.tf32.f32 "
        "{%0,%1,%2,%3}, {%4,%5,%6,%7}, {%8,%9}, {%0,%1,%2,%3};\n"
        : "+f"(c[0]), "+f"(c[1]), "+f"(c[2]), "+f"(c[3])
        : "r"(a0), "r"(a1), "r"(a2), "r"(a3), "r"(b0), "r"(b1));
}

// ---------------- time embedding ---------------------------------------------
__global__ void temb_kernel(const float* __restrict__ t,
                            const float* __restrict__ tW1, const float* __restrict__ tb1,
                            const float* __restrict__ tW2, const float* __restrict__ tb2) {
    __shared__ float hid[C];
    int j = threadIdx.x;
    float tv = t[0];
    hid[j] = fmaxf(tv * tW1[j] + tb1[j], 0.0f);
    __syncthreads();
    float s = tb2[j];
#pragma unroll 8
    for (int i = 0; i < C; i++) s += hid[i] * tW2[i * C + j];
    g_temb[j] = s;
}

// ---------------- degree / dinv / CSR ----------------------------------------
__global__ void degi_init_kernel(int N) {
    int i = blockIdx.x * blockDim.x + threadIdx.x;
    if (i < N) g_degi[i] = 0;
}
__global__ void deg_count_kernel(const int* __restrict__ dst, int E) {
    int e = blockIdx.x * blockDim.x + threadIdx.x;
    if (e < E) atomicAdd(&g_degi[dst[e]], 1);
}
__global__ void dinv_kernel(int N) {
    int i = blockIdx.x * blockDim.x + threadIdx.x;
    if (i < N) g_dinv[i] = rsqrtf((float)g_degi[i] + 1.0f);   // +1 self loop
}

// exclusive scan over g_degi -> g_off (3 kernels)
__global__ void scan_part_kernel(int N) {
    __shared__ int sh[256];
    int t = threadIdx.x;
    int i = blockIdx.x * 256 + t;
    int v = (i < N) ? g_degi[i] : 0;
    sh[t] = v;
    __syncthreads();
#pragma unroll
    for (int off = 1; off < 256; off <<= 1) {
        int x = (t >= off) ? sh[t - off] : 0;
        __syncthreads();
        sh[t] += x;
        __syncthreads();
    }
    if (i < N) g_off[i] = sh[t] - v;          // exclusive within block
    if (t == 255) g_bsum[blockIdx.x] = sh[t]; // block total
}
__global__ void scan_top_kernel(int nb) {
    __shared__ int sh[512];
    int t = threadIdx.x;
    int v = (t < nb) ? g_bsum[t] : 0;
    sh[t] = v;
    __syncthreads();
#pragma unroll
    for (int off = 1; off < 512; off <<= 1) {
        int x = (t >= off) ? sh[t - off] : 0;
        __syncthreads();
        sh[t] += x;
        __syncthreads();
    }
    if (t < nb) g_bsum[t] = sh[t] - v;        // exclusive block offsets
}
__global__ void scan_add_kernel(int N) {
    int i = blockIdx.x * blockDim.x + threadIdx.x;
    if (i < N) {
        int o = g_off[i] + g_bsum[blockIdx.x * 256 / 256 == 0 ? 0 : 0]; // placeholder (fixed below)
        o = g_off[i] + g_bsum[i >> 8];
        g_off[i] = o;
        g_cur[i] = o;
        if (i == N - 1) g_off[N] = o + g_degi[i];
    }
}
__global__ void csr_fill_kernel(const int* __restrict__ src, const int* __restrict__ dst, int E) {
    int e = blockIdx.x * blockDim.x + threadIdx.x;
    if (e >= E) return;
    int s = src[e], d = dst[e];
    int p = atomicAdd(&g_cur[d], 1);
    g_csr_src[p] = s;
    g_csr_coef[p] = g_dinv[s] * g_dinv[d];
}

// ---------------- W prep: split into tf32 big/small, fragment-major ----------
// layout: for W[k][n]: kstep=k>>3, ntile=n>>3, warpN=ntile>>2, j=ntile&3, q=j>>1
//         lane=(n&7)*4+(k&3), r=(j&1)*2+((k>>2)&1)
//         idx = ((kstep*4+warpN)*2+q)*128 + lane*4 + r
__global__ void prep_w_kernel(const float* __restrict__ W1, const float* __restrict__ W2) {
    int id = blockIdx.x * blockDim.x + threadIdx.x;
    if (id >= 2 * 16384) return;
    int mat = id >> 14;
    int el = id & 16383;
    int k = el >> 7, n = el & 127;
    float v = (mat ? W2 : W1)[el];
    unsigned big = f2tf(v);
    float bf = __uint_as_float(big);
    unsigned small = f2tf(v - bf);
    int kstep = k >> 3, ntile = n >> 3;
    int warpN = ntile >> 2, j = ntile & 3, q = j >> 1;
    int lane = (n & 7) * 4 + (k & 3);
    int r = (j & 1) * 2 + ((k >> 2) & 1);
    int idx = ((kstep * 4 + warpN) * 2 + q) * 128 + lane * 4 + r;
    g_wb[mat][idx] = __uint_as_float(big);
    g_ws[mat][idx] = __uint_as_float(small);
}

// ---------------- GEMM: out[M,128] = (A (+temb)) @ W, 3xTF32 mma.sync --------
__global__ void __launch_bounds__(GEMM_THREADS, 1)
gemm_tf32_kernel(const float* __restrict__ A,
                 const float* __restrict__ wb, const float* __restrict__ ws,
                 float* __restrict__ out, int M, int ntiles, int add_temb) {
    extern __shared__ float smem[];
    float* Wb = smem;
    float* Ws = smem + 16384;
    float* Ab = smem + 32768;
    float* As = smem + 40960;
    int tid = threadIdx.x, lane = tid & 31, wid = tid >> 5;
    int warpM = wid >> 2, warpN = wid & 3;

    // copy W fragments (contiguous)
    {
        const float4* s1 = (const float4*)wb;
        const float4* s2 = (const float4*)ws;
        float4* d1 = (float4*)Wb;
        float4* d2 = (float4*)Ws;
#pragma unroll
        for (int i = 0; i < 8; i++) {
            d1[tid + i * 512] = s1[tid + i * 512];
            d2[tid + i * 512] = s2[tid + i * 512];
        }
    }

    int tile = blockIdx.x;
    float4 pf[4];
    if (tile < ntiles) {
#pragma unroll
        for (int i = 0; i < 4; i++) {
            int idx = tid + i * 512;
            int row = tile * BM + (idx >> 5);
            pf[i] = (row < M) ? ((const float4*)A)[(size_t)row * C4 + (idx & 31)]
                              : make_float4(0.f, 0.f, 0.f, 0.f);
        }
    }

    while (tile < ntiles) {
        __syncthreads();   // previous tile's MMA reads done

        // stage A: add temb, split tf32 big/small, swizzled fragment-major STS
#pragma unroll
        for (int i = 0; i < 4; i++) {
            int idx = tid + i * 512;
            int r = idx >> 5, c4 = idx & 31;
            float4 v = pf[i];
            if (add_temb) {
                float4 tv = ((const float4*)g_temb)[c4];
                v.x += tv.x; v.y += tv.y; v.z += tv.z; v.w += tv.w;
            }
            int kstep = c4 >> 1, khigh = c4 & 1;
            int wM = r >> 4, rr = r & 15, g = rr & 7, hi = rr >> 3;
            int slab = kstep * 4 + wM;
            int ks7 = kstep & 7;
            int reg = hi + 2 * khigh;
            float fv[4] = {v.x, v.y, v.z, v.w};
#pragma unroll
            for (int e = 0; e < 4; e++) {
                int lane_s = g * 4 + e;
                int o = slab * 128 + ((lane_s ^ ks7) * 4) + reg;
                unsigned big = f2tf(fv[e]);
                float bf = __uint_as_float(big);
                unsigned small = f2tf(fv[e] - bf);
                Ab[o] = bf;
                As[o] = __uint_as_float(small);
            }
        }
        __syncthreads();

        int next = tile + gridDim.x;
        if (next < ntiles) {
#pragma unroll
            for (int i = 0; i < 4; i++) {
                int idx = tid + i * 512;
                int row = next * BM + (idx >> 5);
                pf[i] = (row < M) ? ((const float4*)A)[(size_t)row * C4 + (idx & 31)]
                                  : make_float4(0.f, 0.f, 0.f, 0.f);
            }
        }

        float acc[4][4];
#pragma unroll
        for (int j = 0; j < 4; j++)
#pragma unroll
            for (int x = 0; x < 4; x++) acc[j][x] = 0.f;

        const uint4* Ab4 = (const uint4*)Ab;
        const uint4* As4 = (const uint4*)As;
        const uint4* Wb4 = (const uint4*)Wb;
        const uint4* Ws4 = (const uint4*)Ws;

#pragma unroll
        for (int ks = 0; ks < 16; ks++) {
            int slabA = ks * 4 + warpM;
            uint4 av = Ab4[slabA * 32 + (lane ^ (ks & 7))];
            uint4 sv = As4[slabA * 32 + (lane ^ (ks & 7))];
#pragma unroll
            for (int q = 0; q < 2; q++) {
                int slabB = (ks * 4 + warpN) * 2 + q;
                uint4 bb = Wb4[slabB * 32 + lane];
                uint4 bs = Ws4[slabB * 32 + lane];
                int j0 = 2 * q, j1 = 2 * q + 1;
                mma8(acc[j0], av.x, av.y, av.z, av.w, bb.x, bb.y);
                mma8(acc[j0], av.x, av.y, av.z, av.w, bs.x, bs.y);
                mma8(acc[j0], sv.x, sv.y, sv.z, sv.w, bb.x, bb.y);
                mma8(acc[j1], av.x, av.y, av.z, av.w, bb.z, bb.w);
                mma8(acc[j1], av.x, av.y, av.z, av.w, bs.z, bs.w);
                mma8(acc[j1], sv.x, sv.y, sv.z, sv.w, bb.z, bb.w);
            }
        }

        // epilogue
        {
            int g = lane >> 2, t4 = lane & 3;
            int row0 = tile * BM + warpM * 16 + g;
#pragma unroll
            for (int j = 0; j < 4; j++) {
                int col = (warpN * 4 + j) * 8 + t4 * 2;
                if (row0 < M)
                    *(float2*)(out + (size_t)row0 * C + col) = make_float2(acc[j][0], acc[j][1]);
                if (row0 + 8 < M)
                    *(float2*)(out + (size_t)(row0 + 8) * C + col) = make_float2(acc[j][2], acc[j][3]);
            }
        }
        tile = next;
    }
}

// ---------------- aggregation: CSR gather + self + bias (+ LN + ReLU) --------
__global__ void agg_kernel(const float* __restrict__ x, float* __restrict__ out,
                           const float* __restrict__ bias,
                           const float* __restrict__ lnw, const float* __restrict__ lnb,
                           int N, int do_ln) {
    int row = (blockIdx.x * blockDim.x + threadIdx.x) >> 5;
    int lane = threadIdx.x & 31;
    if (row >= N) return;
    float di = g_dinv[row];
    float di2 = di * di;
    float4 acc = ((const float4*)x)[(size_t)row * C4 + lane];
    float4 b = ((const float4*)bias)[lane];
    acc.x = acc.x * di2 + b.x;
    acc.y = acc.y * di2 + b.y;
    acc.z = acc.z * di2 + b.z;
    acc.w = acc.w * di2 + b.w;

    int e = g_off[row], e1 = g_off[row + 1];
    for (; e + 1 < e1; e += 2) {
        int s0 = g_csr_src[e], s1 = g_csr_src[e + 1];
        float c0 = g_csr_coef[e], c1 = g_csr_coef[e + 1];
        float4 v0 = ((const float4*)x)[(size_t)s0 * C4 + lane];
        float4 v1 = ((const float4*)x)[(size_t)s1 * C4 + lane];
        acc.x += c0 * v0.x + c1 * v1.x;
        acc.y += c0 * v0.y + c1 * v1.y;
        acc.z += c0 * v0.z + c1 * v1.z;
        acc.w += c0 * v0.w + c1 * v1.w;
    }
    if (e < e1) {
        int s0 = g_csr_src[e];
        float c0 = g_csr_coef[e];
        float4 v0 = ((const float4*)x)[(size_t)s0 * C4 + lane];
        acc.x += c0 * v0.x;
        acc.y += c0 * v0.y;
        acc.z += c0 * v0.z;
        acc.w += c0 * v0.w;
    }

    if (do_ln) {
        float s = acc.x + acc.y + acc.z + acc.w;
#pragma unroll
        for (int o = 16; o > 0; o >>= 1) s += __shfl_xor_sync(0xFFFFFFFFu, s, o);
        float mu = s * (1.0f / 128.0f);
        float dx = acc.x - mu, dy = acc.y - mu, dz = acc.z - mu, dw = acc.w - mu;
        float sq = dx * dx + dy * dy + dz * dz + dw * dw;
#pragma unroll
        for (int o = 16; o > 0; o >>= 1) sq += __shfl_xor_sync(0xFFFFFFFFu, sq, o);
        float rstd = rsqrtf(sq * (1.0f / 128.0f) + 1e-5f);
        float4 w = ((const float4*)lnw)[lane];
        float4 lb = ((const float4*)lnb)[lane];
        acc.x = fmaxf(dx * rstd * w.x + lb.x, 0.0f);
        acc.y = fmaxf(dy * rstd * w.y + lb.y, 0.0f);
        acc.z = fmaxf(dz * rstd * w.z + lb.z, 0.0f);
        acc.w = fmaxf(dw * rstd * w.w + lb.w, 0.0f);
    }
    ((float4*)out)[(size_t)row * C4 + lane] = acc;
}

// ---------------- launcher ---------------------------------------------------
extern "C" void kernel_launch(void* const* d_in, const int* in_sizes, int n_in,
                              void* d_out, int out_size) {
    const float* h_noisy = (const float*)d_in[0];
    const int*   edge    = (const int*)  d_in[1];
    const float* t       = (const float*)d_in[2];
    const float* tW1     = (const float*)d_in[3];
    const float* tb1     = (const float*)d_in[4];
    const float* tW2     = (const float*)d_in[5];
    const float* tb2     = (const float*)d_in[6];
    const float* W1      = (const float*)d_in[7];
    const float* b1      = (const float*)d_in[8];
    const float* W2      = (const float*)d_in[9];
    const float* b2      = (const float*)d_in[10];
    const float* ln_w    = (const float*)d_in[11];
    const float* ln_b    = (const float*)d_in[12];
    float* out = (float*)d_out;

    int N = in_sizes[0] / C;
    int E = in_sizes[1] / 2;
    const int* src = edge;
    const int* dst = edge + E;

    float *bufA, *bufB, *wb, *ws;
    cudaGetSymbolAddress((void**)&bufA, g_bufA);
    cudaGetSymbolAddress((void**)&bufB, g_bufB);
    cudaGetSymbolAddress((void**)&wb, g_wb);
    cudaGetSymbolAddress((void**)&ws, g_ws);

    cudaFuncSetAttribute(gemm_tf32_kernel, cudaFuncAttributeMaxDynamicSharedMemorySize, GEMM_SMEM);

    int nblkN = (N + 255) / 256;       // 391
    int nblkE = (E + 255) / 256;
    int ntiles = (N + BM - 1) / BM;
    int row_blocks = (N * 32 + 255) / 256;

    // time embedding + W prep (independent)
    temb_kernel<<<1, C>>>(t, tW1, tb1, tW2, tb2);
    prep_w_kernel<<<(2 * 16384 + 255) / 256, 256>>>(W1, W2);

    // degree -> dinv -> CSR
    degi_init_kernel<<<nblkN, 256>>>(N);
    deg_count_kernel<<<nblkE, 256>>>(dst, E);
    dinv_kernel<<<nblkN, 256>>>(N);
    scan_part_kernel<<<nblkN, 256>>>(N);
    scan_top_kernel<<<1, 512>>>(nblkN);
    scan_add_kernel<<<nblkN, 256>>>(N);
    csr_fill_kernel<<<nblkE, 256>>>(src, dst, E);

    // layer 1: gemm (h + temb) @ W1 -> bufA ; aggregate + LN + ReLU -> bufB
    gemm_tf32_kernel<<<148, GEMM_THREADS, GEMM_SMEM>>>(h_noisy, wb, ws, bufA, N, ntiles, 1);
    agg_kernel<<<row_blocks, 256>>>(bufA, bufB, b1, ln_w, ln_b, N, 1);

    // layer 2: gemm bufB @ W2 -> bufA ; aggregate -> out
    gemm_tf32_kernel<<<148, GEMM_THREADS, GEMM_SMEM>>>(bufB, wb + 16384, ws + 16384, bufA, N, ntiles, 0);
    agg_kernel<<<row_blocks, 256>>>(bufA, out, b2, nullptr, nullptr, N, 0);
}

// round 3
// speedup vs baseline: 2.1074x; 1.1648x over previous
#include <cuda_runtime.h>
#include <cuda_bf16.h>
#include <cstdint>

#define C 128
#define C4 32
#define MAX_N 100000
#define MAX_E 640000
#define BM 64
#define GEMM_THREADS 512
// u32 layout: Whi 64*132, Wlo 64*132, Ahi 32*132, Alo 32*132
#define W_SLAB_U32 132
#define W_U32 (64 * W_SLAB_U32)      // 8448
#define A_U32 (32 * W_SLAB_U32)      // 4224
#define GEMM_SMEM ((2 * W_U32 + 2 * A_U32) * 4)   // 101376 B

// ---------------- scratch (device globals) -----------------------------------
__device__ float g_temb[C];
__device__ int   g_degi[MAX_N];
__device__ float g_dinv[MAX_N];
__device__ int   g_off[MAX_N + 1];
__device__ int   g_cur[MAX_N];
__device__ int   g_bsum[512];
__device__ int   g_csr_src[MAX_E];
__device__ float g_csr_coef[MAX_E];
__device__ float g_bufA[(size_t)MAX_N * C];
__device__ float g_bufB[(size_t)MAX_N * C];
__device__ unsigned g_whi[2][W_U32];
__device__ unsigned g_wlo[2][W_U32];

// ---------------- helpers ----------------------------------------------------
__device__ __forceinline__ unsigned pack_bf2(float a, float b) {
    __nv_bfloat162 v = __floats2bfloat162_rn(a, b);
    return *reinterpret_cast<unsigned*>(&v);
}
__device__ __forceinline__ float bf_hi(float x) {
    return __bfloat162float(__float2bfloat16(x));
}
__device__ __forceinline__ void mma16(float* c, unsigned a0, unsigned a1,
                                      unsigned a2, unsigned a3,
                                      unsigned b0, unsigned b1) {
    asm volatile(
        "mma.sync.aligned.m16n8k16.row.col.f32.bf16.bf16.f32 "
        "{%0,%1,%2,%3}, {%4,%5,%6,%7}, {%8,%9}, {%0,%1,%2,%3};\n"
        : "+f"(c[0]), "+f"(c[1]), "+f"(c[2]), "+f"(c[3])
        : "r"(a0), "r"(a1), "r"(a2), "r"(a3), "r"(b0), "r"(b1));
}

// ---------------- fused setup: W split/pack + temb + deg zero ----------------
// blocks 0..63   : pack W1/W2 into bf16 hi/lo fragment-major (8192 u32/mat)
// block  64      : time embedding MLP
// blocks 65..455 : zero g_degi
__global__ void setup_kernel(const float* __restrict__ W1, const float* __restrict__ W2,
                             const float* __restrict__ t,
                             const float* __restrict__ tW1, const float* __restrict__ tb1,
                             const float* __restrict__ tW2, const float* __restrict__ tb2,
                             int N) {
    int b = blockIdx.x;
    if (b < 64) {
        int id = b * 256 + threadIdx.x;       // 0..16383
        int mat = id >> 13;
        int u = id & 8191;                    // logical u32 index
        int slab = u >> 7;                    // 0..63
        int lane = (u >> 2) & 31;
        int reg = u & 3;
        int q = slab & 1, warpN = (slab >> 1) & 3, ks = slab >> 3;
        int jq = reg >> 1, khigh = reg & 1;
        int n = (warpN * 4 + q * 2 + jq) * 8 + (lane >> 2);
        int k = ks * 16 + khigh * 8 + (lane & 3) * 2;
        const float* W = mat ? W2 : W1;
        float v0 = W[k * C + n];
        float v1 = W[(k + 1) * C + n];
        float h0 = bf_hi(v0), h1 = bf_hi(v1);
        int gi = slab * W_SLAB_U32 + lane * 4 + reg;
        g_whi[mat][gi] = pack_bf2(h0, h1);
        g_wlo[mat][gi] = pack_bf2(v0 - h0, v1 - h1);
    } else if (b == 64) {
        __shared__ float hid[C];
        int j = threadIdx.x;
        if (j < C) {
            float tv = t[0];
            hid[j] = fmaxf(tv * tW1[j] + tb1[j], 0.0f);
        }
        __syncthreads();
        if (j < C) {
            float s = tb2[j];
#pragma unroll 8
            for (int i = 0; i < C; i++) s += hid[i] * tW2[i * C + j];
            g_temb[j] = s;
        }
    } else {
        int i = (b - 65) * 256 + threadIdx.x;
        if (i < N) g_degi[i] = 0;
    }
}

// ---------------- degree count -----------------------------------------------
__global__ void deg_count_kernel(const int* __restrict__ dst, int E) {
    int e = blockIdx.x * blockDim.x + threadIdx.x;
    if (e < E) atomicAdd(&g_degi[dst[e]], 1);
}

// ---------------- scan part + dinv -------------------------------------------
__global__ void scan_part_kernel(int N) {
    __shared__ int sh[256];
    int tt = threadIdx.x;
    int i = blockIdx.x * 256 + tt;
    int v = (i < N) ? g_degi[i] : 0;
    if (i < N) g_dinv[i] = rsqrtf((float)v + 1.0f);
    sh[tt] = v;
    __syncthreads();
#pragma unroll
    for (int off = 1; off < 256; off <<= 1) {
        int x = (tt >= off) ? sh[tt - off] : 0;
        __syncthreads();
        sh[tt] += x;
        __syncthreads();
    }
    if (i < N) g_off[i] = sh[tt] - v;
    if (tt == 255) g_bsum[blockIdx.x] = sh[tt];
}
__global__ void scan_top_kernel(int nb) {
    __shared__ int sh[512];
    int tt = threadIdx.x;
    int v = (tt < nb) ? g_bsum[tt] : 0;
    sh[tt] = v;
    __syncthreads();
#pragma unroll
    for (int off = 1; off < 512; off <<= 1) {
        int x = (tt >= off) ? sh[tt - off] : 0;
        __syncthreads();
        sh[tt] += x;
        __syncthreads();
    }
    if (tt < nb) g_bsum[tt] = sh[tt] - v;
}
__global__ void scan_add_kernel(int N) {
    int i = blockIdx.x * blockDim.x + threadIdx.x;
    if (i < N) {
        int o = g_off[i] + g_bsum[i >> 8];
        g_off[i] = o;
        g_cur[i] = o;
        if (i == N - 1) g_off[N] = o + g_degi[i];
    }
}
__global__ void csr_fill_kernel(const int* __restrict__ src, const int* __restrict__ dst, int E) {
    int e = blockIdx.x * blockDim.x + threadIdx.x;
    if (e >= E) return;
    int s = src[e], d = dst[e];
    int p = atomicAdd(&g_cur[d], 1);
    g_csr_src[p] = s;
    g_csr_coef[p] = g_dinv[s] * g_dinv[d];
}

// ---------------- GEMM: out[M,128] = (A (+temb)) @ W, 3xBF16 mma.sync --------
__global__ void __launch_bounds__(GEMM_THREADS)
gemm_bf16_kernel(const float* __restrict__ A,
                 const unsigned* __restrict__ whi, const unsigned* __restrict__ wlo,
                 float* __restrict__ out, int M, int ntiles, int add_temb) {
    extern __shared__ unsigned smem[];
    unsigned* Whi = smem;
    unsigned* Wlo = smem + W_U32;
    unsigned* Ahi = smem + 2 * W_U32;
    unsigned* Alo = smem + 2 * W_U32 + A_U32;
    int tid = threadIdx.x, lane = tid & 31, wid = tid >> 5;
    int warpM = wid >> 2, warpN = wid & 3;

    // copy W fragments (2112 uint4 each)
    {
        const uint4* s1 = (const uint4*)whi;
        const uint4* s2 = (const uint4*)wlo;
        uint4* d1 = (uint4*)Whi;
        uint4* d2 = (uint4*)Wlo;
        for (int i = tid; i < W_U32 / 4; i += GEMM_THREADS) {
            d1[i] = s1[i];
            d2[i] = s2[i];
        }
    }

    int tile = blockIdx.x;
    float4 pf[4];
    if (tile < ntiles) {
#pragma unroll
        for (int i = 0; i < 4; i++) {
            int idx = tid + i * 512;
            int row = tile * BM + (idx >> 5);
            pf[i] = (row < M) ? ((const float4*)A)[(size_t)row * C4 + (idx & 31)]
                              : make_float4(0.f, 0.f, 0.f, 0.f);
        }
    }

    while (tile < ntiles) {
        __syncthreads();   // previous tile's MMA smem reads done (+ W copy, iter 0)

        // stage A: temb add, bf16 hi/lo split, fragment-major swizzled STS
#pragma unroll
        for (int i = 0; i < 4; i++) {
            int idx = tid + i * 512;
            int r = idx >> 5, c4 = idx & 31;
            float4 v = pf[i];
            if (add_temb) {
                float4 tv = ((const float4*)g_temb)[c4];
                v.x += tv.x; v.y += tv.y; v.z += tv.z; v.w += tv.w;
            }
            int wM = r >> 4, rloc = r & 15;
            int ks = c4 >> 2;
            int slab = ks * 4 + wM;
            int p0 = (2 * c4) & 7;
            int lane0 = (rloc & 7) * 4 + (p0 & 3);
            int reg = (rloc >> 3) + 2 * (p0 >> 2);
            float hx = bf_hi(v.x), hy = bf_hi(v.y), hz = bf_hi(v.z), hw = bf_hi(v.w);
            int base = slab * W_SLAB_U32 + lane0 * 4 + reg;
            Ahi[base]     = pack_bf2(hx, hy);
            Ahi[base + 4] = pack_bf2(hz, hw);
            Alo[base]     = pack_bf2(v.x - hx, v.y - hy);
            Alo[base + 4] = pack_bf2(v.z - hz, v.w - hw);
        }
        __syncthreads();

        int next = tile + gridDim.x;
        if (next < ntiles) {
#pragma unroll
            for (int i = 0; i < 4; i++) {
                int idx = tid + i * 512;
                int row = next * BM + (idx >> 5);
                pf[i] = (row < M) ? ((const float4*)A)[(size_t)row * C4 + (idx & 31)]
                                  : make_float4(0.f, 0.f, 0.f, 0.f);
            }
        }

        float acc[4][4];
#pragma unroll
        for (int j = 0; j < 4; j++)
#pragma unroll
            for (int x = 0; x < 4; x++) acc[j][x] = 0.f;

        const uint4* Ahi4 = (const uint4*)Ahi;
        const uint4* Alo4 = (const uint4*)Alo;
        const uint4* Whi4 = (const uint4*)Whi;
        const uint4* Wlo4 = (const uint4*)Wlo;

#pragma unroll
        for (int ks = 0; ks < 8; ks++) {
            int slabA = ks * 4 + warpM;
            uint4 ah = Ahi4[slabA * (W_SLAB_U32 / 4) + lane];
            uint4 al = Alo4[slabA * (W_SLAB_U32 / 4) + lane];
#pragma unroll
            for (int q = 0; q < 2; q++) {
                int slabB = (ks * 4 + warpN) * 2 + q;
                uint4 wh = Whi4[slabB * (W_SLAB_U32 / 4) + lane];
                uint4 wl = Wlo4[slabB * (W_SLAB_U32 / 4) + lane];
                int j0 = 2 * q, j1 = 2 * q + 1;
                mma16(acc[j0], ah.x, ah.y, ah.z, ah.w, wh.x, wh.y);
                mma16(acc[j0], ah.x, ah.y, ah.z, ah.w, wl.x, wl.y);
                mma16(acc[j0], al.x, al.y, al.z, al.w, wh.x, wh.y);
                mma16(acc[j1], ah.x, ah.y, ah.z, ah.w, wh.z, wh.w);
                mma16(acc[j1], ah.x, ah.y, ah.z, ah.w, wl.z, wl.w);
                mma16(acc[j1], al.x, al.y, al.z, al.w, wh.z, wh.w);
            }
        }

        // epilogue
        {
            int g = lane >> 2, t4 = lane & 3;
            int row0 = tile * BM + warpM * 16 + g;
#pragma unroll
            for (int j = 0; j < 4; j++) {
                int col = (warpN * 4 + j) * 8 + t4 * 2;
                if (row0 < M)
                    *(float2*)(out + (size_t)row0 * C + col) = make_float2(acc[j][0], acc[j][1]);
                if (row0 + 8 < M)
                    *(float2*)(out + (size_t)(row0 + 8) * C + col) = make_float2(acc[j][2], acc[j][3]);
            }
        }
        tile = next;
    }
}

// ---------------- aggregation: CSR gather + self + bias (+ LN + ReLU) --------
__global__ void agg_kernel(const float* __restrict__ x, float* __restrict__ out,
                           const float* __restrict__ bias,
                           const float* __restrict__ lnw, const float* __restrict__ lnb,
                           int N, int do_ln) {
    int row = (blockIdx.x * blockDim.x + threadIdx.x) >> 5;
    int lane = threadIdx.x & 31;
    if (row >= N) return;
    float di = g_dinv[row];
    float di2 = di * di;
    float4 acc = ((const float4*)x)[(size_t)row * C4 + lane];
    float4 b = ((const float4*)bias)[lane];
    acc.x = acc.x * di2 + b.x;
    acc.y = acc.y * di2 + b.y;
    acc.z = acc.z * di2 + b.z;
    acc.w = acc.w * di2 + b.w;

    int e = g_off[row], e1 = g_off[row + 1];
    for (; e + 1 < e1; e += 2) {
        int s0 = g_csr_src[e], s1 = g_csr_src[e + 1];
        float c0 = g_csr_coef[e], c1 = g_csr_coef[e + 1];
        float4 v0 = ((const float4*)x)[(size_t)s0 * C4 + lane];
        float4 v1 = ((const float4*)x)[(size_t)s1 * C4 + lane];
        acc.x += c0 * v0.x + c1 * v1.x;
        acc.y += c0 * v0.y + c1 * v1.y;
        acc.z += c0 * v0.z + c1 * v1.z;
        acc.w += c0 * v0.w + c1 * v1.w;
    }
    if (e < e1) {
        int s0 = g_csr_src[e];
        float c0 = g_csr_coef[e];
        float4 v0 = ((const float4*)x)[(size_t)s0 * C4 + lane];
        acc.x += c0 * v0.x;
        acc.y += c0 * v0.y;
        acc.z += c0 * v0.z;
        acc.w += c0 * v0.w;
    }

    if (do_ln) {
        float s = acc.x + acc.y + acc.z + acc.w;
#pragma unroll
        for (int o = 16; o > 0; o >>= 1) s += __shfl_xor_sync(0xFFFFFFFFu, s, o);
        float mu = s * (1.0f / 128.0f);
        float dx = acc.x - mu, dy = acc.y - mu, dz = acc.z - mu, dw = acc.w - mu;
        float sq = dx * dx + dy * dy + dz * dz + dw * dw;
#pragma unroll
        for (int o = 16; o > 0; o >>= 1) sq += __shfl_xor_sync(0xFFFFFFFFu, sq, o);
        float rstd = rsqrtf(sq * (1.0f / 128.0f) + 1e-5f);
        float4 w = ((const float4*)lnw)[lane];
        float4 lb = ((const float4*)lnb)[lane];
        acc.x = fmaxf(dx * rstd * w.x + lb.x, 0.0f);
        acc.y = fmaxf(dy * rstd * w.y + lb.y, 0.0f);
        acc.z = fmaxf(dz * rstd * w.z + lb.z, 0.0f);
        acc.w = fmaxf(dw * rstd * w.w + lb.w, 0.0f);
    }
    ((float4*)out)[(size_t)row * C4 + lane] = acc;
}

// ---------------- launcher ---------------------------------------------------
extern "C" void kernel_launch(void* const* d_in, const int* in_sizes, int n_in,
                              void* d_out, int out_size) {
    const float* h_noisy = (const float*)d_in[0];
    const int*   edge    = (const int*)  d_in[1];
    const float* t       = (const float*)d_in[2];
    const float* tW1     = (const float*)d_in[3];
    const float* tb1     = (const float*)d_in[4];
    const float* tW2     = (const float*)d_in[5];
    const float* tb2     = (const float*)d_in[6];
    const float* W1      = (const float*)d_in[7];
    const float* b1      = (const float*)d_in[8];
    const float* W2      = (const float*)d_in[9];
    const float* b2      = (const float*)d_in[10];
    const float* ln_w    = (const float*)d_in[11];
    const float* ln_b    = (const float*)d_in[12];
    float* out = (float*)d_out;

    int N = in_sizes[0] / C;
    int E = in_sizes[1] / 2;
    const int* src = edge;
    const int* dst = edge + E;

    float *bufA, *bufB;
    unsigned *whi, *wlo;
    cudaGetSymbolAddress((void**)&bufA, g_bufA);
    cudaGetSymbolAddress((void**)&bufB, g_bufB);
    cudaGetSymbolAddress((void**)&whi, g_whi);
    cudaGetSymbolAddress((void**)&wlo, g_wlo);

    cudaFuncSetAttribute(gemm_bf16_kernel, cudaFuncAttributeMaxDynamicSharedMemorySize, GEMM_SMEM);

    int nblkN = (N + 255) / 256;       // 391
    int nblkE = (E + 255) / 256;
    int ntiles = (N + BM - 1) / BM;
    int row_blocks = (N * 32 + 255) / 256;

    // 1. fused setup (W pack + temb + deg zero)
    setup_kernel<<<65 + nblkN, 256>>>(W1, W2, t, tW1, tb1, tW2, tb2, N);
    // 2. degree count
    deg_count_kernel<<<nblkE, 256>>>(dst, E);
    // 3. scan part + dinv
    scan_part_kernel<<<nblkN, 256>>>(N);
    // 4. gemm1 (profiled slot): (h + temb) @ W1 -> bufA
    gemm_bf16_kernel<<<148, GEMM_THREADS, GEMM_SMEM>>>(h_noisy, whi, wlo, bufA, N, ntiles, 1);
    // 5-7. finish CSR
    scan_top_kernel<<<1, 512>>>(nblkN);
    scan_add_kernel<<<nblkN, 256>>>(N);
    csr_fill_kernel<<<nblkE, 256>>>(src, dst, E);
    // 8. aggregate + LN + ReLU -> bufB
    agg_kernel<<<row_blocks, 256>>>(bufA, bufB, b1, ln_w, ln_b, N, 1);
    // 9. gemm2: bufB @ W2 -> bufA
    gemm_bf16_kernel<<<148, GEMM_THREADS, GEMM_SMEM>>>(bufB, whi + W_U32, wlo + W_U32, bufA, N, ntiles, 0);
    // 10. aggregate -> out
    agg_kernel<<<row_blocks, 256>>>(bufA, out, b2, nullptr, nullptr, N, 0);
}

// round 4
// speedup vs baseline: 2.2975x; 1.0902x over previous
#include <cuda_runtime.h>
#include <cuda_bf16.h>
#include <cstdint>

#define C 128
#define C4 32
#define MAX_N 100000
#define MAX_E 640000
#define BM 32
#define GEMM_THREADS 256
#define A_SLAB 132                 // u32 per slab (128 + 4 pad)
#define A_U32 (16 * A_SLAB)        // 2112 u32 per buffer per hi/lo

// ---------------- scratch (device globals) -----------------------------------
__device__ float g_temb[C];
__device__ int   g_degi[MAX_N];
__device__ float g_dinv[MAX_N];
__device__ int   g_off[MAX_N + 1];
__device__ int   g_cur[MAX_N];
__device__ int   g_bsum[512];
__device__ int   g_csr_src[MAX_E];
__device__ float g_csr_coef[MAX_E];
__device__ float g_bufA[(size_t)MAX_N * C];
__device__ float g_bufB[(size_t)MAX_N * C];
__device__ uint2 g_whi[2][4096];   // [mat][(ks*16+nf)*32+lane] = {b0,b1}
__device__ uint2 g_wlo[2][4096];

// ---------------- helpers ----------------------------------------------------
__device__ __forceinline__ unsigned pack_bf2(float a, float b) {
    __nv_bfloat162 v = __floats2bfloat162_rn(a, b);
    return *reinterpret_cast<unsigned*>(&v);
}
__device__ __forceinline__ float bf_hi(float x) {
    return __bfloat162float(__float2bfloat16(x));
}
__device__ __forceinline__ void mma16(float* c, unsigned a0, unsigned a1,
                                      unsigned a2, unsigned a3,
                                      unsigned b0, unsigned b1) {
    asm volatile(
        "mma.sync.aligned.m16n8k16.row.col.f32.bf16.bf16.f32 "
        "{%0,%1,%2,%3}, {%4,%5,%6,%7}, {%8,%9}, {%0,%1,%2,%3};\n"
        : "+f"(c[0]), "+f"(c[1]), "+f"(c[2]), "+f"(c[3])
        : "r"(a0), "r"(a1), "r"(a2), "r"(a3), "r"(b0), "r"(b1));
}

// ---------------- fused setup: W pack + temb + deg zero ----------------------
// blocks 0..31  : pack W1/W2 into bf16 hi/lo mma-fragment layout
// block  32     : time embedding MLP
// blocks 33..   : zero g_degi
__global__ void setup_kernel(const float* __restrict__ W1, const float* __restrict__ W2,
                             const float* __restrict__ t,
                             const float* __restrict__ tW1, const float* __restrict__ tb1,
                             const float* __restrict__ tW2, const float* __restrict__ tb2,
                             int N) {
    int b = blockIdx.x;
    if (b < 32) {
        int id = b * 256 + threadIdx.x;   // 0..8191
        int mat = id >> 12;
        int rem = id & 4095;
        int ks = rem >> 9, nf = (rem >> 5) & 15, lane = rem & 31;
        int k0 = ks * 16 + (lane & 3) * 2;
        int n = nf * 8 + (lane >> 2);
        const float* W = mat ? W2 : W1;
        float v00 = W[k0 * C + n];
        float v01 = W[(k0 + 1) * C + n];
        float v10 = W[(k0 + 8) * C + n];
        float v11 = W[(k0 + 9) * C + n];
        float h00 = bf_hi(v00), h01 = bf_hi(v01), h10 = bf_hi(v10), h11 = bf_hi(v11);
        int idx = (ks * 16 + nf) * 32 + lane;
        g_whi[mat][idx] = make_uint2(pack_bf2(h00, h01), pack_bf2(h10, h11));
        g_wlo[mat][idx] = make_uint2(pack_bf2(v00 - h00, v01 - h01),
                                     pack_bf2(v10 - h10, v11 - h11));
    } else if (b == 32) {
        __shared__ float hid[C];
        int j = threadIdx.x;
        if (j < C) {
            float tv = t[0];
            hid[j] = fmaxf(tv * tW1[j] + tb1[j], 0.0f);
        }
        __syncthreads();
        if (j < C) {
            float s = tb2[j];
#pragma unroll 8
            for (int i = 0; i < C; i++) s += hid[i] * tW2[i * C + j];
            g_temb[j] = s;
        }
    } else {
        int i = (b - 33) * 256 + threadIdx.x;
        if (i < N) g_degi[i] = 0;
    }
}

// ---------------- degree count -----------------------------------------------
__global__ void deg_count_kernel(const int* __restrict__ dst, int E) {
    int e = blockIdx.x * blockDim.x + threadIdx.x;
    if (e < E) atomicAdd(&g_degi[dst[e]], 1);
}

// ---------------- scan part + dinv -------------------------------------------
__global__ void scan_part_kernel(int N) {
    __shared__ int sh[256];
    int tt = threadIdx.x;
    int i = blockIdx.x * 256 + tt;
    int v = (i < N) ? g_degi[i] : 0;
    if (i < N) g_dinv[i] = rsqrtf((float)v + 1.0f);
    sh[tt] = v;
    __syncthreads();
#pragma unroll
    for (int off = 1; off < 256; off <<= 1) {
        int x = (tt >= off) ? sh[tt - off] : 0;
        __syncthreads();
        sh[tt] += x;
        __syncthreads();
    }
    if (i < N) g_off[i] = sh[tt] - v;
    if (tt == 255) g_bsum[blockIdx.x] = sh[tt];
}
__global__ void scan_top_kernel(int nb) {
    __shared__ int sh[512];
    int tt = threadIdx.x;
    int v = (tt < nb) ? g_bsum[tt] : 0;
    sh[tt] = v;
    __syncthreads();
#pragma unroll
    for (int off = 1; off < 512; off <<= 1) {
        int x = (tt >= off) ? sh[tt - off] : 0;
        __syncthreads();
        sh[tt] += x;
        __syncthreads();
    }
    if (tt < nb) g_bsum[tt] = sh[tt] - v;
}
__global__ void scan_add_kernel(int N) {
    int i = blockIdx.x * blockDim.x + threadIdx.x;
    if (i < N) {
        int o = g_off[i] + g_bsum[i >> 8];
        g_off[i] = o;
        g_cur[i] = o;
        if (i == N - 1) g_off[N] = o + g_degi[i];
    }
}
__global__ void csr_fill_kernel(const int* __restrict__ src, const int* __restrict__ dst, int E) {
    int e = blockIdx.x * blockDim.x + threadIdx.x;
    if (e >= E) return;
    int s = src[e], d = dst[e];
    int p = atomicAdd(&g_cur[d], 1);
    g_csr_src[p] = s;
    g_csr_coef[p] = g_dinv[s] * g_dinv[d];
}

// ---------------- GEMM: out[M,128] = (A (+temb)) @ W, 3xBF16, W in regs ------
__global__ void __launch_bounds__(GEMM_THREADS, 2)
gemm_bf16_kernel(const float* __restrict__ A,
                 const uint2* __restrict__ whi, const uint2* __restrict__ wlo,
                 float* __restrict__ out, int M, int ntiles, int add_temb) {
    __shared__ unsigned Ah[2][A_U32];
    __shared__ unsigned Al[2][A_U32];
    int tid = threadIdx.x, lane = tid & 31, warpN = tid >> 5;   // warpN 0..7

    // W fragments for this warp's 16 columns, held in registers for the whole kernel
    uint2 wh[8][2], wl[8][2];
#pragma unroll
    for (int ks = 0; ks < 8; ks++)
#pragma unroll
        for (int j = 0; j < 2; j++) {
            int idx = (ks * 16 + warpN * 2 + j) * 32 + lane;
            wh[ks][j] = whi[idx];
            wl[ks][j] = wlo[idx];
        }

    // per-thread loop-invariant staging geometry (c4 = tid&31 for all i)
    int c4 = tid & 31;
    int ks_t = c4 >> 2;
    int khigh = (c4 >> 1) & 1;
    int kp0 = (c4 & 1) * 2;
    float4 tmb = make_float4(0.f, 0.f, 0.f, 0.f);
    if (add_temb) tmb = ((const float4*)g_temb)[c4];

    int G = gridDim.x;
    int tile = blockIdx.x;
    float4 pf[4];

#define LOADPF(T)                                                              \
    {                                                                          \
        _Pragma("unroll") for (int i = 0; i < 4; i++) {                        \
            int row = (T) * BM + warpN + i * 8;                                \
            pf[i] = (row < M) ? ((const float4*)A)[(size_t)row * C4 + c4]      \
                              : make_float4(0.f, 0.f, 0.f, 0.f);               \
        }                                                                      \
    }

#define STAGE(S)                                                               \
    {                                                                          \
        _Pragma("unroll") for (int i = 0; i < 4; i++) {                        \
            int r = warpN + i * 8;                                             \
            int rloc = r & 15, mf = r >> 4;                                    \
            float4 v = pf[i];                                                  \
            v.x += tmb.x; v.y += tmb.y; v.z += tmb.z; v.w += tmb.w;            \
            float hx = bf_hi(v.x), hy = bf_hi(v.y);                            \
            float hz = bf_hi(v.z), hw = bf_hi(v.w);                            \
            int slot = (ks_t * 2 + mf) * A_SLAB + ((rloc & 7) * 4 + kp0) * 4   \
                       + (rloc >> 3) + 2 * khigh;                              \
            Ah[S][slot]     = pack_bf2(hx, hy);                                \
            Ah[S][slot + 4] = pack_bf2(hz, hw);                                \
            Al[S][slot]     = pack_bf2(v.x - hx, v.y - hy);                    \
            Al[S][slot + 4] = pack_bf2(v.z - hz, v.w - hw);                    \
        }                                                                      \
    }

    if (tile < ntiles) {
        LOADPF(tile);
        STAGE(0);
        if (tile + G < ntiles) LOADPF(tile + G);
    }
    int s = 0;

    while (tile < ntiles) {
        __syncthreads();   // buf[s] staging complete across all warps
        if (tile + G < ntiles) {
            STAGE(s ^ 1);
            if (tile + 2 * G < ntiles) LOADPF(tile + 2 * G);
        }

        float acc[2][2][4];
#pragma unroll
        for (int mf = 0; mf < 2; mf++)
#pragma unroll
            for (int j = 0; j < 2; j++)
#pragma unroll
                for (int x = 0; x < 4; x++) acc[mf][j][x] = 0.f;

        const uint4* Ah4 = (const uint4*)Ah[s];
        const uint4* Al4 = (const uint4*)Al[s];
#pragma unroll
        for (int ks = 0; ks < 8; ks++) {
#pragma unroll
            for (int mf = 0; mf < 2; mf++) {
                uint4 ah = Ah4[(ks * 2 + mf) * (A_SLAB / 4) + lane];
                uint4 al = Al4[(ks * 2 + mf) * (A_SLAB / 4) + lane];
#pragma unroll
                for (int j = 0; j < 2; j++) {
                    mma16(acc[mf][j], ah.x, ah.y, ah.z, ah.w, wh[ks][j].x, wh[ks][j].y);
                    mma16(acc[mf][j], ah.x, ah.y, ah.z, ah.w, wl[ks][j].x, wl[ks][j].y);
                    mma16(acc[mf][j], al.x, al.y, al.z, al.w, wh[ks][j].x, wh[ks][j].y);
                }
            }
        }

        // epilogue
        {
            int g = lane >> 2, cc = lane & 3;
#pragma unroll
            for (int mf = 0; mf < 2; mf++) {
                int row0 = tile * BM + mf * 16 + g;
#pragma unroll
                for (int j = 0; j < 2; j++) {
                    int col = (warpN * 2 + j) * 8 + cc * 2;
                    if (row0 < M)
                        *(float2*)(out + (size_t)row0 * C + col) =
                            make_float2(acc[mf][j][0], acc[mf][j][1]);
                    if (row0 + 8 < M)
                        *(float2*)(out + (size_t)(row0 + 8) * C + col) =
                            make_float2(acc[mf][j][2], acc[mf][j][3]);
                }
            }
        }
        s ^= 1;
        tile += G;
    }
#undef LOADPF
#undef STAGE
}

// ---------------- aggregation: CSR gather + self + bias (+ LN + ReLU) --------
__global__ void agg_kernel(const float* __restrict__ x, float* __restrict__ out,
                           const float* __restrict__ bias,
                           const float* __restrict__ lnw, const float* __restrict__ lnb,
                           int N, int do_ln) {
    int row = (blockIdx.x * blockDim.x + threadIdx.x) >> 5;
    int lane = threadIdx.x & 31;
    if (row >= N) return;
    float di = g_dinv[row];
    float di2 = di * di;
    float4 acc = ((const float4*)x)[(size_t)row * C4 + lane];
    float4 b = ((const float4*)bias)[lane];
    acc.x = acc.x * di2 + b.x;
    acc.y = acc.y * di2 + b.y;
    acc.z = acc.z * di2 + b.z;
    acc.w = acc.w * di2 + b.w;

    int e = g_off[row], e1 = g_off[row + 1];
    for (; e + 1 < e1; e += 2) {
        int s0 = g_csr_src[e], s1 = g_csr_src[e + 1];
        float c0 = g_csr_coef[e], c1 = g_csr_coef[e + 1];
        float4 v0 = ((const float4*)x)[(size_t)s0 * C4 + lane];
        float4 v1 = ((const float4*)x)[(size_t)s1 * C4 + lane];
        acc.x += c0 * v0.x + c1 * v1.x;
        acc.y += c0 * v0.y + c1 * v1.y;
        acc.z += c0 * v0.z + c1 * v1.z;
        acc.w += c0 * v0.w + c1 * v1.w;
    }
    if (e < e1) {
        int s0 = g_csr_src[e];
        float c0 = g_csr_coef[e];
        float4 v0 = ((const float4*)x)[(size_t)s0 * C4 + lane];
        acc.x += c0 * v0.x;
        acc.y += c0 * v0.y;
        acc.z += c0 * v0.z;
        acc.w += c0 * v0.w;
    }

    if (do_ln) {
        float s = acc.x + acc.y + acc.z + acc.w;
#pragma unroll
        for (int o = 16; o > 0; o >>= 1) s += __shfl_xor_sync(0xFFFFFFFFu, s, o);
        float mu = s * (1.0f / 128.0f);
        float dx = acc.x - mu, dy = acc.y - mu, dz = acc.z - mu, dw = acc.w - mu;
        float sq = dx * dx + dy * dy + dz * dz + dw * dw;
#pragma unroll
        for (int o = 16; o > 0; o >>= 1) sq += __shfl_xor_sync(0xFFFFFFFFu, sq, o);
        float rstd = rsqrtf(sq * (1.0f / 128.0f) + 1e-5f);
        float4 w = ((const float4*)lnw)[lane];
        float4 lb = ((const float4*)lnb)[lane];
        acc.x = fmaxf(dx * rstd * w.x + lb.x, 0.0f);
        acc.y = fmaxf(dy * rstd * w.y + lb.y, 0.0f);
        acc.z = fmaxf(dz * rstd * w.z + lb.z, 0.0f);
        acc.w = fmaxf(dw * rstd * w.w + lb.w, 0.0f);
    }
    ((float4*)out)[(size_t)row * C4 + lane] = acc;
}

// ---------------- launcher ---------------------------------------------------
extern "C" void kernel_launch(void* const* d_in, const int* in_sizes, int n_in,
                              void* d_out, int out_size) {
    const float* h_noisy = (const float*)d_in[0];
    const int*   edge    = (const int*)  d_in[1];
    const float* t       = (const float*)d_in[2];
    const float* tW1     = (const float*)d_in[3];
    const float* tb1     = (const float*)d_in[4];
    const float* tW2     = (const float*)d_in[5];
    const float* tb2     = (const float*)d_in[6];
    const float* W1      = (const float*)d_in[7];
    const float* b1      = (const float*)d_in[8];
    const float* W2      = (const float*)d_in[9];
    const float* b2      = (const float*)d_in[10];
    const float* ln_w    = (const float*)d_in[11];
    const float* ln_b    = (const float*)d_in[12];
    float* out = (float*)d_out;

    int N = in_sizes[0] / C;
    int E = in_sizes[1] / 2;
    const int* src = edge;
    const int* dst = edge + E;

    float *bufA, *bufB;
    uint2 *whi, *wlo;
    cudaGetSymbolAddress((void**)&bufA, g_bufA);
    cudaGetSymbolAddress((void**)&bufB, g_bufB);
    cudaGetSymbolAddress((void**)&whi, g_whi);
    cudaGetSymbolAddress((void**)&wlo, g_wlo);

    int nblkN = (N + 255) / 256;       // 391
    int nblkE = (E + 255) / 256;
    int ntiles = (N + BM - 1) / BM;    // 3125
    int row_blocks = (N * 32 + 255) / 256;

    // 1. fused setup (W pack + temb + deg zero)
    setup_kernel<<<33 + nblkN, 256>>>(W1, W2, t, tW1, tb1, tW2, tb2, N);
    // 2. degree count
    deg_count_kernel<<<nblkE, 256>>>(dst, E);
    // 3. scan part + dinv
    scan_part_kernel<<<nblkN, 256>>>(N);
    // 4. gemm1 (profiled slot): (h + temb) @ W1 -> bufA
    gemm_bf16_kernel<<<296, GEMM_THREADS>>>(h_noisy, whi, wlo, bufA, N, ntiles, 1);
    // 5-7. finish CSR
    scan_top_kernel<<<1, 512>>>(nblkN);
    scan_add_kernel<<<nblkN, 256>>>(N);
    csr_fill_kernel<<<nblkE, 256>>>(src, dst, E);
    // 8. aggregate + LN + ReLU -> bufB
    agg_kernel<<<row_blocks, 256>>>(bufA, bufB, b1, ln_w, ln_b, N, 1);
    // 9. gemm2: bufB @ W2 -> bufA
    gemm_bf16_kernel<<<296, GEMM_THREADS>>>(bufB, whi + 4096, wlo + 4096, bufA, N, ntiles, 0);
    // 10. aggregate -> out
    agg_kernel<<<row_blocks, 256>>>(bufA, out, b2, nullptr, nullptr, N, 0);
}